// round 13
// baseline (speedup 1.0000x reference)
#include <cuda_runtime.h>
#include <cuda_bf16.h>

// GLoCELayerOutProp: B=4, T=1024, D=2048, N=8, S=8, H=8, ETA=1.
//
// R12 = R11 + 32 tokens/block (512 threads, 1 block/SM, grid 128):
//  - GEMM: warp = 128-wide K-range, computes BOTH 16-token M-tiles with the
//    same register-held B fragments -> B L2 traffic per token halves.
//  - phase 2: 16 x 128-dim D-slices over 32 tokens -> updT/dgnT reuse doubles.
//  - ysum [16][32][80] fp32 (160KB) aliases the bf16 x-tile in dynamic smem.

#define DD    2048
#define NCON  8
#define SR    8
#define HR    8
#define TBT   32
#define NT    512
#define NWARP 16
#define YP    80
#define XBP   (DD + 8)
#define NCHUNK 8

typedef unsigned int u32;

// Bfrag: [kslice(8)][kk16(16)][j(9)][lane(32)][uint2]  (288KB of bf16)
__device__ __nv_bfloat16 g_Bf[8 * 16 * 9 * 32 * 2 * 2];
__device__ float g_updT[NCON][HR][DD];
__device__ float g_dgnT[NCON][HR][DD];
__device__ float g_muWp[NCON][NCHUNK][SR];
__device__ float g_mun2p[NCON][NCHUNK];

__device__ __forceinline__ float warp_sum(float v) {
    #pragma unroll
    for (int o = 16; o > 0; o >>= 1) v += __shfl_xor_sync(0xffffffffu, v, o);
    return v;
}

__device__ __forceinline__ int bf_idx(int col, int k) {
    const int w  = k >> 8;
    const int kk = (k & 255) >> 4;
    const int off = k & 15;
    const int bslot = off >> 3;
    const int c4 = (off & 7) >> 1;
    const int half = off & 1;
    const int g = col & 7;
    const int j = col >> 3;
    return ((((w * 16 + kk) * 9 + j) * 32 + (g * 4 + c4)) * 2 + bslot) * 2 + half;
}

// ---- prologue: grid 64 = 8 concepts x 8 chunks (unchanged from R11) ----
__global__ void __launch_bounds__(256)
k_prep(const float* __restrict__ Wsel, const float* __restrict__ mu,
       const float* __restrict__ upd, const float* __restrict__ dgn) {
    __shared__ float red[8][SR];
    __shared__ float redm[8];
    const int n     = blockIdx.x >> 3;
    const int chunk = blockIdx.x & 7;
    const int tid   = threadIdx.x;
    const int warp  = tid >> 5;
    const int lane  = tid & 31;
    const int d     = chunk * 256 + tid;

    const float mv = __ldg(mu + n * DD + d);
    const float4 wa = __ldg(reinterpret_cast<const float4*>(
                                Wsel + (long)n * DD * SR + (long)d * SR));
    const float4 wb = __ldg(reinterpret_cast<const float4*>(
                                Wsel + (long)n * DD * SR + (long)d * SR + 4));

    g_Bf[bf_idx(n * 8 + 0, d)] = __float2bfloat16_rn(wa.x);
    g_Bf[bf_idx(n * 8 + 1, d)] = __float2bfloat16_rn(wa.y);
    g_Bf[bf_idx(n * 8 + 2, d)] = __float2bfloat16_rn(wa.z);
    g_Bf[bf_idx(n * 8 + 3, d)] = __float2bfloat16_rn(wa.w);
    g_Bf[bf_idx(n * 8 + 4, d)] = __float2bfloat16_rn(wb.x);
    g_Bf[bf_idx(n * 8 + 5, d)] = __float2bfloat16_rn(wb.y);
    g_Bf[bf_idx(n * 8 + 6, d)] = __float2bfloat16_rn(wb.z);
    g_Bf[bf_idx(n * 8 + 7, d)] = __float2bfloat16_rn(wb.w);
    g_Bf[bf_idx(64 + n,    d)] = __float2bfloat16_rn(mv);

    {
        const float4 ua = __ldg(reinterpret_cast<const float4*>(
                                    upd + (long)n * DD * HR + (long)d * HR));
        const float4 ub = __ldg(reinterpret_cast<const float4*>(
                                    upd + (long)n * DD * HR + (long)d * HR + 4));
        g_updT[n][0][d] = ua.x;  g_updT[n][1][d] = ua.y;
        g_updT[n][2][d] = ua.z;  g_updT[n][3][d] = ua.w;
        g_updT[n][4][d] = ub.x;  g_updT[n][5][d] = ub.y;
        g_updT[n][6][d] = ub.z;  g_updT[n][7][d] = ub.w;
        const float4 ga = __ldg(reinterpret_cast<const float4*>(
                                    dgn + (long)n * DD * HR + (long)d * HR));
        const float4 gb = __ldg(reinterpret_cast<const float4*>(
                                    dgn + (long)n * DD * HR + (long)d * HR + 4));
        g_dgnT[n][0][d] = ga.x;  g_dgnT[n][1][d] = ga.y;
        g_dgnT[n][2][d] = ga.z;  g_dgnT[n][3][d] = ga.w;
        g_dgnT[n][4][d] = gb.x;  g_dgnT[n][5][d] = gb.y;
        g_dgnT[n][6][d] = gb.z;  g_dgnT[n][7][d] = gb.w;
    }

    float acc[SR];
    acc[0] = mv * wa.x;  acc[1] = mv * wa.y;
    acc[2] = mv * wa.z;  acc[3] = mv * wa.w;
    acc[4] = mv * wb.x;  acc[5] = mv * wb.y;
    acc[6] = mv * wb.z;  acc[7] = mv * wb.w;
    float m2 = mv * mv;

    #pragma unroll
    for (int s = 0; s < SR; s++) {
        const float v = warp_sum(acc[s]);
        if (lane == 0) red[warp][s] = v;
    }
    m2 = warp_sum(m2);
    if (lane == 0) redm[warp] = m2;
    __syncthreads();
    if (tid < SR) {
        float s = 0.f;
        #pragma unroll
        for (int w = 0; w < 8; w++) s += red[w][tid];
        g_muWp[n][chunk][tid] = s;
    }
    if (tid == 0) {
        float s = 0.f;
        #pragma unroll
        for (int w = 0; w < 8; w++) s += redm[w];
        g_mun2p[n][chunk] = s;
    }
}

// ---- main: 512 threads, 32 tokens/block ----
__global__ void __launch_bounds__(NT, 1)
gloce_main(const float* __restrict__ x,
           const float* __restrict__ center,
           const float* __restrict__ slope,
           const float* __restrict__ bias_w,
           const float* __restrict__ debias_w,
           float* __restrict__ out)
{
    extern __shared__ char dsm[];
    __nv_bfloat16* xb = reinterpret_cast<__nv_bfloat16*>(dsm);   // [TBT][XBP] 131.6KB
    float* ysum = reinterpret_cast<float*>(dsm);                 // [16][TBT][YP] 160KB (aliases)

    __shared__ float yfin[TBT][YP];
    __shared__ float nx2[TBT];
    __shared__ float gates[TBT][NCON];
    __shared__ float ssel[TBT];
    __shared__ int   csel[TBT];
    __shared__ float hpart[TBT][NWARP][HR];
    __shared__ float hf_s[TBT][HR];
    __shared__ float s_muW[64];
    __shared__ float s_mun2[NCON];

    const int tid  = threadIdx.x;
    const int warp = tid >> 5;
    const int lane = tid & 31;
    const long tok0 = (long)blockIdx.x * TBT;

    // fold prologue partials
    if (tid < 64) {
        const int n = tid >> 3, s = tid & 7;
        float v = 0.f;
        #pragma unroll
        for (int c = 0; c < NCHUNK; c++) v += g_muWp[n][c][s];
        s_muW[tid] = v;
    } else if (tid < 72) {
        const int n = tid - 64;
        float v = 0.f;
        #pragma unroll
        for (int c = 0; c < NCHUNK; c++) v += g_mun2p[n][c];
        s_mun2[n] = v;
    }

    // ---- stage x: warp w -> tokens 2w, 2w+1 ----
    #pragma unroll
    for (int q = 0; q < 2; q++) {
        const int t = 2 * warp + q;
        const float4* xr = reinterpret_cast<const float4*>(x + (tok0 + t) * DD);
        float nrm = 0.f;
        #pragma unroll 4
        for (int i = 0; i < 16; i++) {
            const float4 v = __ldg(xr + i * 32 + lane);
            nrm = fmaf(v.x, v.x, nrm);
            nrm = fmaf(v.y, v.y, nrm);
            nrm = fmaf(v.z, v.z, nrm);
            nrm = fmaf(v.w, v.w, nrm);
            __nv_bfloat162 b0 = __float22bfloat162_rn(make_float2(v.x, v.y));
            __nv_bfloat162 b1 = __float22bfloat162_rn(make_float2(v.z, v.w));
            uint2 pk = make_uint2(*reinterpret_cast<u32*>(&b0),
                                  *reinterpret_cast<u32*>(&b1));
            *reinterpret_cast<uint2*>(&xb[t * XBP + i * 128 + lane * 4]) = pk;
        }
        nrm = warp_sum(nrm);
        if (lane == 0) nx2[t] = nrm;
    }
    __syncthreads();

    // ---- GEMM: warp = 128-wide K range, BOTH M-tiles share B regs ----
    {
        const int ks = warp & 7;              // kslice (matches Bf layout w)
        const int kh = warp >> 3;             // which half of the kslice
        float acc[2][9][4];
        #pragma unroll
        for (int mt = 0; mt < 2; mt++)
            #pragma unroll
            for (int j = 0; j < 9; j++)
                #pragma unroll
                for (int r = 0; r < 4; r++) acc[mt][j][r] = 0.f;

        const int g = lane >> 2;
        const int c4 = lane & 3;
        const uint2* bf = reinterpret_cast<const uint2*>(g_Bf) +
                          ((long)ks * 16 + kh * 8) * 9 * 32 + lane;

        #pragma unroll 1
        for (int kk = 0; kk < 8; kk++) {
            const int kbase = ks * 256 + kh * 128 + kk * 16;
            u32 a[2][4];
            #pragma unroll
            for (int mt = 0; mt < 2; mt++) {
                const int r0 = mt * 16 + g;
                a[mt][0] = *reinterpret_cast<const u32*>(&xb[r0 * XBP + kbase + 2 * c4]);
                a[mt][1] = *reinterpret_cast<const u32*>(&xb[(r0 + 8) * XBP + kbase + 2 * c4]);
                a[mt][2] = *reinterpret_cast<const u32*>(&xb[r0 * XBP + kbase + 2 * c4 + 8]);
                a[mt][3] = *reinterpret_cast<const u32*>(&xb[(r0 + 8) * XBP + kbase + 2 * c4 + 8]);
            }
            const uint2* bfk = bf + kk * 9 * 32;
            #pragma unroll
            for (int j = 0; j < 9; j++) {
                const uint2 bb = __ldg(bfk + j * 32);
                #pragma unroll
                for (int mt = 0; mt < 2; mt++) {
                    asm volatile(
                        "mma.sync.aligned.m16n8k16.row.col.f32.bf16.bf16.f32 "
                        "{%0,%1,%2,%3}, {%4,%5,%6,%7}, {%8,%9}, {%0,%1,%2,%3};"
                        : "+f"(acc[mt][j][0]), "+f"(acc[mt][j][1]),
                          "+f"(acc[mt][j][2]), "+f"(acc[mt][j][3])
                        : "r"(a[mt][0]), "r"(a[mt][1]), "r"(a[mt][2]), "r"(a[mt][3]),
                          "r"(bb.x), "r"(bb.y));
                }
            }
        }
        __syncthreads();   // all warps done reading xb -> alias as ysum

        float* yw = ysum + warp * TBT * YP;
        #pragma unroll
        for (int mt = 0; mt < 2; mt++) {
            const int r0 = mt * 16 + g;
            #pragma unroll
            for (int j = 0; j < 9; j++) {
                const int cc = j * 8 + 2 * c4;
                *reinterpret_cast<float2*>(&yw[r0 * YP + cc]) =
                    make_float2(acc[mt][j][0], acc[mt][j][1]);
                *reinterpret_cast<float2*>(&yw[(r0 + 8) * YP + cc]) =
                    make_float2(acc[mt][j][2], acc[mt][j][3]);
            }
        }
    }
    __syncthreads();

    // ---- K-reduction: 32x80 outputs over 16 partials ----
    #pragma unroll
    for (int i = 0; i < 5; i++) {
        const int o = tid + i * NT;           // < 2560
        const int t = o / YP, c = o % YP;
        float s = 0.f;
        #pragma unroll
        for (int w = 0; w < NWARP; w++) s += ysum[(w * TBT + t) * YP + c];
        yfin[t][c] = s;
    }
    __syncthreads();

    // ---- scores + gates: 256 threads ----
    if (tid < TBT * NCON) {
        const int t = tid >> 3, n = tid & 7;
        const float xmu = yfin[t][64 + n];
        const float denom = nx2[t] - 2.f * xmu + s_mun2[n];
        float sc = 0.f;
        #pragma unroll
        for (int s = 0; s < SR; s++) {
            const float v = yfin[t][n * 8 + s] - s_muW[n * 8 + s];
            sc = fmaf(v, v, sc);
        }
        const float z = __ldg(slope + n) * (sc / denom - __ldg(center + n));
        gates[t][n] = 1.f / (1.f + __expf(-z));
    }
    __syncthreads();

    if (tid < TBT) {
        float best = gates[tid][0];
        int bi = 0;
        #pragma unroll
        for (int n = 1; n < NCON; n++) {
            const float gv = gates[tid][n];
            if (gv > best) { best = gv; bi = n; }
        }
        ssel[tid] = best;
        csel[tid] = bi;
    }
    __syncthreads();

    // ---- phase 2: warp = 128-dim D-slice, 8 groups of 4 tokens ----
    const int d0 = warp * (DD / NWARP);

    #pragma unroll 1
    for (int g2 = 0; g2 < 8; g2++) {
        int sc4[4];
        #pragma unroll
        for (int tt = 0; tt < 4; tt++) sc4[tt] = csel[g2 * 4 + tt];

        float h[4][HR];
        #pragma unroll
        for (int tt = 0; tt < 4; tt++)
            #pragma unroll
            for (int j = 0; j < HR; j++) h[tt][j] = 0.f;

        #pragma unroll 1
        for (int c = 0; c < NCON; c++) {
            bool any = false;
            #pragma unroll
            for (int tt = 0; tt < 4; tt++) any |= (sc4[tt] == c);
            if (!any) continue;

            const float* updT = &g_updT[c][0][0];
            const float* dbc  = debias_w + c * DD;
            #pragma unroll 2
            for (int i = 0; i < 4; i++) {
                const int d = d0 + lane + 32 * i;
                const float db = __ldg(dbc + d);
                float u[HR];
                #pragma unroll
                for (int j = 0; j < HR; j++) u[j] = __ldg(updT + j * DD + d);
                #pragma unroll
                for (int tt = 0; tt < 4; tt++) {
                    if (sc4[tt] == c) {
                        const int t = g2 * 4 + tt;
                        const float xd = __ldg(x + (tok0 + t) * DD + d) - db;
                        #pragma unroll
                        for (int j = 0; j < HR; j++)
                            h[tt][j] = fmaf(u[j], xd, h[tt][j]);
                    }
                }
            }
        }
        #pragma unroll
        for (int tt = 0; tt < 4; tt++) {
            #pragma unroll
            for (int j = 0; j < HR; j++) {
                const float v = warp_sum(h[tt][j]);
                if (lane == 0) hpart[g2 * 4 + tt][warp][j] = v;
            }
        }
    }
    __syncthreads();

    // ---- cross-warp h reduction: 256 (t,j) pairs ----
    if (tid < TBT * HR) {
        const int t = tid >> 3, j = tid & 7;
        float s = 0.f;
        #pragma unroll
        for (int w = 0; w < NWARP; w++) s += hpart[t][w][j];
        hf_s[t][j] = s;
    }
    __syncthreads();

    // ---- output ----
    #pragma unroll 1
    for (int g2 = 0; g2 < 8; g2++) {
        int   sc4[4];
        float ss4[4];
        float hf[4][HR];
        #pragma unroll
        for (int tt = 0; tt < 4; tt++) {
            sc4[tt] = csel[g2 * 4 + tt];
            ss4[tt] = ssel[g2 * 4 + tt];
            #pragma unroll
            for (int j = 0; j < HR; j++) hf[tt][j] = hf_s[g2 * 4 + tt][j];
        }

        #pragma unroll 1
        for (int c = 0; c < NCON; c++) {
            bool any = false;
            #pragma unroll
            for (int tt = 0; tt < 4; tt++) any |= (sc4[tt] == c);
            if (!any) continue;

            const float* dgnT = &g_dgnT[c][0][0];
            const float* bnc  = bias_w + c * DD;
            #pragma unroll 2
            for (int i = 0; i < 4; i++) {
                const int d = d0 + lane + 32 * i;
                const float bv = __ldg(bnc + d);
                float gv[HR];
                #pragma unroll
                for (int j = 0; j < HR; j++) gv[j] = __ldg(dgnT + j * DD + d);
                #pragma unroll
                for (int tt = 0; tt < 4; tt++) {
                    if (sc4[tt] == c) {
                        const int t = g2 * 4 + tt;
                        float dv = gv[0] * hf[tt][0];
                        #pragma unroll
                        for (int j = 1; j < HR; j++)
                            dv = fmaf(gv[j], hf[tt][j], dv);
                        const float s = ss4[tt];
                        const float xv = __ldg(x + (tok0 + t) * DD + d);
                        out[(tok0 + t) * DD + d] = (1.f - s) * xv + s * (bv + dv);
                    }
                }
            }
        }
    }
}

extern "C" void kernel_launch(void* const* d_in, const int* in_sizes, int n_in,
                              void* d_out, int out_size) {
    const float* x      = (const float*)d_in[0];
    const float* Wsel   = (const float*)d_in[1];
    const float* mu     = (const float*)d_in[2];
    const float* center = (const float*)d_in[3];
    const float* slope  = (const float*)d_in[4];
    const float* upd    = (const float*)d_in[5];
    const float* dgn    = (const float*)d_in[6];
    const float* bias_w = (const float*)d_in[7];
    const float* debias = (const float*)d_in[8];
    float* out = (float*)d_out;

    const int tokens = in_sizes[0] / DD;                        // 4096
    const int grid   = tokens / TBT;                            // 128

    size_t smem_tile = (size_t)TBT * XBP * sizeof(__nv_bfloat16);      // 131584
    size_t smem_ysum = (size_t)NWARP * TBT * YP * sizeof(float);       // 163840
    size_t smem = smem_tile > smem_ysum ? smem_tile : smem_ysum;

    k_prep<<<NCON * NCHUNK, 256>>>(Wsel, mu, upd, dgn);

    cudaFuncSetAttribute(gloce_main,
                         cudaFuncAttributeMaxDynamicSharedMemorySize, (int)smem);
    gloce_main<<<grid, NT, smem>>>(x, center, slope, bias_w, debias, out);
}

// round 14
// speedup vs baseline: 1.0161x; 1.0161x over previous
#include <cuda_runtime.h>
#include <cuda_bf16.h>

// GLoCELayerOutProp: B=4, T=1024, D=2048, N=8, S=8, H=8, ETA=1.
//
// R12 = R11 + 32 tokens/block (512 threads, 1 block/SM, grid 128):
//  - GEMM: warp = 128-wide K-range, computes BOTH 16-token M-tiles with the
//    same register-held B fragments -> B L2 traffic per token halves.
//  - phase 2: 16 x 128-dim D-slices over 32 tokens -> updT/dgnT reuse doubles.
//  - ysum [16][32][80] fp32 (160KB) aliases the bf16 x-tile in dynamic smem.

#define DD    2048
#define NCON  8
#define SR    8
#define HR    8
#define TBT   32
#define NT    512
#define NWARP 16
#define YP    80
#define XBP   (DD + 8)
#define NCHUNK 8

typedef unsigned int u32;

// Bfrag: [kslice(8)][kk16(16)][j(9)][lane(32)][uint2]  (288KB of bf16)
__device__ __nv_bfloat16 g_Bf[8 * 16 * 9 * 32 * 2 * 2];
__device__ float g_updT[NCON][HR][DD];
__device__ float g_dgnT[NCON][HR][DD];
__device__ float g_muWp[NCON][NCHUNK][SR];
__device__ float g_mun2p[NCON][NCHUNK];

__device__ __forceinline__ float warp_sum(float v) {
    #pragma unroll
    for (int o = 16; o > 0; o >>= 1) v += __shfl_xor_sync(0xffffffffu, v, o);
    return v;
}

__device__ __forceinline__ int bf_idx(int col, int k) {
    const int w  = k >> 8;
    const int kk = (k & 255) >> 4;
    const int off = k & 15;
    const int bslot = off >> 3;
    const int c4 = (off & 7) >> 1;
    const int half = off & 1;
    const int g = col & 7;
    const int j = col >> 3;
    return ((((w * 16 + kk) * 9 + j) * 32 + (g * 4 + c4)) * 2 + bslot) * 2 + half;
}

// ---- prologue: grid 64 = 8 concepts x 8 chunks (unchanged from R11) ----
__global__ void __launch_bounds__(256)
k_prep(const float* __restrict__ Wsel, const float* __restrict__ mu,
       const float* __restrict__ upd, const float* __restrict__ dgn) {
    __shared__ float red[8][SR];
    __shared__ float redm[8];
    const int n     = blockIdx.x >> 3;
    const int chunk = blockIdx.x & 7;
    const int tid   = threadIdx.x;
    const int warp  = tid >> 5;
    const int lane  = tid & 31;
    const int d     = chunk * 256 + tid;

    const float mv = __ldg(mu + n * DD + d);
    const float4 wa = __ldg(reinterpret_cast<const float4*>(
                                Wsel + (long)n * DD * SR + (long)d * SR));
    const float4 wb = __ldg(reinterpret_cast<const float4*>(
                                Wsel + (long)n * DD * SR + (long)d * SR + 4));

    g_Bf[bf_idx(n * 8 + 0, d)] = __float2bfloat16_rn(wa.x);
    g_Bf[bf_idx(n * 8 + 1, d)] = __float2bfloat16_rn(wa.y);
    g_Bf[bf_idx(n * 8 + 2, d)] = __float2bfloat16_rn(wa.z);
    g_Bf[bf_idx(n * 8 + 3, d)] = __float2bfloat16_rn(wa.w);
    g_Bf[bf_idx(n * 8 + 4, d)] = __float2bfloat16_rn(wb.x);
    g_Bf[bf_idx(n * 8 + 5, d)] = __float2bfloat16_rn(wb.y);
    g_Bf[bf_idx(n * 8 + 6, d)] = __float2bfloat16_rn(wb.z);
    g_Bf[bf_idx(n * 8 + 7, d)] = __float2bfloat16_rn(wb.w);
    g_Bf[bf_idx(64 + n,    d)] = __float2bfloat16_rn(mv);

    {
        const float4 ua = __ldg(reinterpret_cast<const float4*>(
                                    upd + (long)n * DD * HR + (long)d * HR));
        const float4 ub = __ldg(reinterpret_cast<const float4*>(
                                    upd + (long)n * DD * HR + (long)d * HR + 4));
        g_updT[n][0][d] = ua.x;  g_updT[n][1][d] = ua.y;
        g_updT[n][2][d] = ua.z;  g_updT[n][3][d] = ua.w;
        g_updT[n][4][d] = ub.x;  g_updT[n][5][d] = ub.y;
        g_updT[n][6][d] = ub.z;  g_updT[n][7][d] = ub.w;
        const float4 ga = __ldg(reinterpret_cast<const float4*>(
                                    dgn + (long)n * DD * HR + (long)d * HR));
        const float4 gb = __ldg(reinterpret_cast<const float4*>(
                                    dgn + (long)n * DD * HR + (long)d * HR + 4));
        g_dgnT[n][0][d] = ga.x;  g_dgnT[n][1][d] = ga.y;
        g_dgnT[n][2][d] = ga.z;  g_dgnT[n][3][d] = ga.w;
        g_dgnT[n][4][d] = gb.x;  g_dgnT[n][5][d] = gb.y;
        g_dgnT[n][6][d] = gb.z;  g_dgnT[n][7][d] = gb.w;
    }

    float acc[SR];
    acc[0] = mv * wa.x;  acc[1] = mv * wa.y;
    acc[2] = mv * wa.z;  acc[3] = mv * wa.w;
    acc[4] = mv * wb.x;  acc[5] = mv * wb.y;
    acc[6] = mv * wb.z;  acc[7] = mv * wb.w;
    float m2 = mv * mv;

    #pragma unroll
    for (int s = 0; s < SR; s++) {
        const float v = warp_sum(acc[s]);
        if (lane == 0) red[warp][s] = v;
    }
    m2 = warp_sum(m2);
    if (lane == 0) redm[warp] = m2;
    __syncthreads();
    if (tid < SR) {
        float s = 0.f;
        #pragma unroll
        for (int w = 0; w < 8; w++) s += red[w][tid];
        g_muWp[n][chunk][tid] = s;
    }
    if (tid == 0) {
        float s = 0.f;
        #pragma unroll
        for (int w = 0; w < 8; w++) s += redm[w];
        g_mun2p[n][chunk] = s;
    }
}

// ---- main: 512 threads, 32 tokens/block ----
__global__ void __launch_bounds__(NT, 1)
gloce_main(const float* __restrict__ x,
           const float* __restrict__ center,
           const float* __restrict__ slope,
           const float* __restrict__ bias_w,
           const float* __restrict__ debias_w,
           float* __restrict__ out)
{
    extern __shared__ char dsm[];
    __nv_bfloat16* xb = reinterpret_cast<__nv_bfloat16*>(dsm);   // [TBT][XBP] 131.6KB
    float* ysum = reinterpret_cast<float*>(dsm);                 // [16][TBT][YP] 160KB (aliases)

    __shared__ float yfin[TBT][YP];
    __shared__ float nx2[TBT];
    __shared__ float gates[TBT][NCON];
    __shared__ float ssel[TBT];
    __shared__ int   csel[TBT];
    __shared__ float hpart[TBT][NWARP][HR];
    __shared__ float hf_s[TBT][HR];
    __shared__ float s_muW[64];
    __shared__ float s_mun2[NCON];

    const int tid  = threadIdx.x;
    const int warp = tid >> 5;
    const int lane = tid & 31;
    const long tok0 = (long)blockIdx.x * TBT;

    // fold prologue partials
    if (tid < 64) {
        const int n = tid >> 3, s = tid & 7;
        float v = 0.f;
        #pragma unroll
        for (int c = 0; c < NCHUNK; c++) v += g_muWp[n][c][s];
        s_muW[tid] = v;
    } else if (tid < 72) {
        const int n = tid - 64;
        float v = 0.f;
        #pragma unroll
        for (int c = 0; c < NCHUNK; c++) v += g_mun2p[n][c];
        s_mun2[n] = v;
    }

    // ---- stage x: warp w -> tokens 2w, 2w+1 ----
    #pragma unroll
    for (int q = 0; q < 2; q++) {
        const int t = 2 * warp + q;
        const float4* xr = reinterpret_cast<const float4*>(x + (tok0 + t) * DD);
        float nrm = 0.f;
        #pragma unroll 4
        for (int i = 0; i < 16; i++) {
            const float4 v = __ldg(xr + i * 32 + lane);
            nrm = fmaf(v.x, v.x, nrm);
            nrm = fmaf(v.y, v.y, nrm);
            nrm = fmaf(v.z, v.z, nrm);
            nrm = fmaf(v.w, v.w, nrm);
            __nv_bfloat162 b0 = __float22bfloat162_rn(make_float2(v.x, v.y));
            __nv_bfloat162 b1 = __float22bfloat162_rn(make_float2(v.z, v.w));
            uint2 pk = make_uint2(*reinterpret_cast<u32*>(&b0),
                                  *reinterpret_cast<u32*>(&b1));
            *reinterpret_cast<uint2*>(&xb[t * XBP + i * 128 + lane * 4]) = pk;
        }
        nrm = warp_sum(nrm);
        if (lane == 0) nx2[t] = nrm;
    }
    __syncthreads();

    // ---- GEMM: warp = 128-wide K range, BOTH M-tiles share B regs ----
    {
        const int ks = warp & 7;              // kslice (matches Bf layout w)
        const int kh = warp >> 3;             // which half of the kslice
        float acc[2][9][4];
        #pragma unroll
        for (int mt = 0; mt < 2; mt++)
            #pragma unroll
            for (int j = 0; j < 9; j++)
                #pragma unroll
                for (int r = 0; r < 4; r++) acc[mt][j][r] = 0.f;

        const int g = lane >> 2;
        const int c4 = lane & 3;
        const uint2* bf = reinterpret_cast<const uint2*>(g_Bf) +
                          ((long)ks * 16 + kh * 8) * 9 * 32 + lane;

        #pragma unroll 1
        for (int kk = 0; kk < 8; kk++) {
            const int kbase = ks * 256 + kh * 128 + kk * 16;
            u32 a[2][4];
            #pragma unroll
            for (int mt = 0; mt < 2; mt++) {
                const int r0 = mt * 16 + g;
                a[mt][0] = *reinterpret_cast<const u32*>(&xb[r0 * XBP + kbase + 2 * c4]);
                a[mt][1] = *reinterpret_cast<const u32*>(&xb[(r0 + 8) * XBP + kbase + 2 * c4]);
                a[mt][2] = *reinterpret_cast<const u32*>(&xb[r0 * XBP + kbase + 2 * c4 + 8]);
                a[mt][3] = *reinterpret_cast<const u32*>(&xb[(r0 + 8) * XBP + kbase + 2 * c4 + 8]);
            }
            const uint2* bfk = bf + kk * 9 * 32;
            #pragma unroll
            for (int j = 0; j < 9; j++) {
                const uint2 bb = __ldg(bfk + j * 32);
                #pragma unroll
                for (int mt = 0; mt < 2; mt++) {
                    asm volatile(
                        "mma.sync.aligned.m16n8k16.row.col.f32.bf16.bf16.f32 "
                        "{%0,%1,%2,%3}, {%4,%5,%6,%7}, {%8,%9}, {%0,%1,%2,%3};"
                        : "+f"(acc[mt][j][0]), "+f"(acc[mt][j][1]),
                          "+f"(acc[mt][j][2]), "+f"(acc[mt][j][3])
                        : "r"(a[mt][0]), "r"(a[mt][1]), "r"(a[mt][2]), "r"(a[mt][3]),
                          "r"(bb.x), "r"(bb.y));
                }
            }
        }
        __syncthreads();   // all warps done reading xb -> alias as ysum

        float* yw = ysum + warp * TBT * YP;
        #pragma unroll
        for (int mt = 0; mt < 2; mt++) {
            const int r0 = mt * 16 + g;
            #pragma unroll
            for (int j = 0; j < 9; j++) {
                const int cc = j * 8 + 2 * c4;
                *reinterpret_cast<float2*>(&yw[r0 * YP + cc]) =
                    make_float2(acc[mt][j][0], acc[mt][j][1]);
                *reinterpret_cast<float2*>(&yw[(r0 + 8) * YP + cc]) =
                    make_float2(acc[mt][j][2], acc[mt][j][3]);
            }
        }
    }
    __syncthreads();

    // ---- K-reduction: 32x80 outputs over 16 partials ----
    #pragma unroll
    for (int i = 0; i < 5; i++) {
        const int o = tid + i * NT;           // < 2560
        const int t = o / YP, c = o % YP;
        float s = 0.f;
        #pragma unroll
        for (int w = 0; w < NWARP; w++) s += ysum[(w * TBT + t) * YP + c];
        yfin[t][c] = s;
    }
    __syncthreads();

    // ---- scores + gates: 256 threads ----
    if (tid < TBT * NCON) {
        const int t = tid >> 3, n = tid & 7;
        const float xmu = yfin[t][64 + n];
        const float denom = nx2[t] - 2.f * xmu + s_mun2[n];
        float sc = 0.f;
        #pragma unroll
        for (int s = 0; s < SR; s++) {
            const float v = yfin[t][n * 8 + s] - s_muW[n * 8 + s];
            sc = fmaf(v, v, sc);
        }
        const float z = __ldg(slope + n) * (sc / denom - __ldg(center + n));
        gates[t][n] = 1.f / (1.f + __expf(-z));
    }
    __syncthreads();

    if (tid < TBT) {
        float best = gates[tid][0];
        int bi = 0;
        #pragma unroll
        for (int n = 1; n < NCON; n++) {
            const float gv = gates[tid][n];
            if (gv > best) { best = gv; bi = n; }
        }
        ssel[tid] = best;
        csel[tid] = bi;
    }
    __syncthreads();

    // ---- phase 2: warp = 128-dim D-slice, 8 groups of 4 tokens ----
    const int d0 = warp * (DD / NWARP);

    #pragma unroll 1
    for (int g2 = 0; g2 < 8; g2++) {
        int sc4[4];
        #pragma unroll
        for (int tt = 0; tt < 4; tt++) sc4[tt] = csel[g2 * 4 + tt];

        float h[4][HR];
        #pragma unroll
        for (int tt = 0; tt < 4; tt++)
            #pragma unroll
            for (int j = 0; j < HR; j++) h[tt][j] = 0.f;

        #pragma unroll 1
        for (int c = 0; c < NCON; c++) {
            bool any = false;
            #pragma unroll
            for (int tt = 0; tt < 4; tt++) any |= (sc4[tt] == c);
            if (!any) continue;

            const float* updT = &g_updT[c][0][0];
            const float* dbc  = debias_w + c * DD;
            #pragma unroll 2
            for (int i = 0; i < 4; i++) {
                const int d = d0 + lane + 32 * i;
                const float db = __ldg(dbc + d);
                float u[HR];
                #pragma unroll
                for (int j = 0; j < HR; j++) u[j] = __ldg(updT + j * DD + d);
                #pragma unroll
                for (int tt = 0; tt < 4; tt++) {
                    if (sc4[tt] == c) {
                        const int t = g2 * 4 + tt;
                        const float xd = __ldg(x + (tok0 + t) * DD + d) - db;
                        #pragma unroll
                        for (int j = 0; j < HR; j++)
                            h[tt][j] = fmaf(u[j], xd, h[tt][j]);
                    }
                }
            }
        }
        #pragma unroll
        for (int tt = 0; tt < 4; tt++) {
            #pragma unroll
            for (int j = 0; j < HR; j++) {
                const float v = warp_sum(h[tt][j]);
                if (lane == 0) hpart[g2 * 4 + tt][warp][j] = v;
            }
        }
    }
    __syncthreads();

    // ---- cross-warp h reduction: 256 (t,j) pairs ----
    if (tid < TBT * HR) {
        const int t = tid >> 3, j = tid & 7;
        float s = 0.f;
        #pragma unroll
        for (int w = 0; w < NWARP; w++) s += hpart[t][w][j];
        hf_s[t][j] = s;
    }
    __syncthreads();

    // ---- output ----
    #pragma unroll 1
    for (int g2 = 0; g2 < 8; g2++) {
        int   sc4[4];
        float ss4[4];
        float hf[4][HR];
        #pragma unroll
        for (int tt = 0; tt < 4; tt++) {
            sc4[tt] = csel[g2 * 4 + tt];
            ss4[tt] = ssel[g2 * 4 + tt];
            #pragma unroll
            for (int j = 0; j < HR; j++) hf[tt][j] = hf_s[g2 * 4 + tt][j];
        }

        #pragma unroll 1
        for (int c = 0; c < NCON; c++) {
            bool any = false;
            #pragma unroll
            for (int tt = 0; tt < 4; tt++) any |= (sc4[tt] == c);
            if (!any) continue;

            const float* dgnT = &g_dgnT[c][0][0];
            const float* bnc  = bias_w + c * DD;
            #pragma unroll 2
            for (int i = 0; i < 4; i++) {
                const int d = d0 + lane + 32 * i;
                const float bv = __ldg(bnc + d);
                float gv[HR];
                #pragma unroll
                for (int j = 0; j < HR; j++) gv[j] = __ldg(dgnT + j * DD + d);
                #pragma unroll
                for (int tt = 0; tt < 4; tt++) {
                    if (sc4[tt] == c) {
                        const int t = g2 * 4 + tt;
                        float dv = gv[0] * hf[tt][0];
                        #pragma unroll
                        for (int j = 1; j < HR; j++)
                            dv = fmaf(gv[j], hf[tt][j], dv);
                        const float s = ss4[tt];
                        const float xv = __ldg(x + (tok0 + t) * DD + d);
                        out[(tok0 + t) * DD + d] = (1.f - s) * xv + s * (bv + dv);
                    }
                }
            }
        }
    }
}

extern "C" void kernel_launch(void* const* d_in, const int* in_sizes, int n_in,
                              void* d_out, int out_size) {
    const float* x      = (const float*)d_in[0];
    const float* Wsel   = (const float*)d_in[1];
    const float* mu     = (const float*)d_in[2];
    const float* center = (const float*)d_in[3];
    const float* slope  = (const float*)d_in[4];
    const float* upd    = (const float*)d_in[5];
    const float* dgn    = (const float*)d_in[6];
    const float* bias_w = (const float*)d_in[7];
    const float* debias = (const float*)d_in[8];
    float* out = (float*)d_out;

    const int tokens = in_sizes[0] / DD;                        // 4096
    const int grid   = tokens / TBT;                            // 128

    size_t smem_tile = (size_t)TBT * XBP * sizeof(__nv_bfloat16);      // 131584
    size_t smem_ysum = (size_t)NWARP * TBT * YP * sizeof(float);       // 163840
    size_t smem = smem_tile > smem_ysum ? smem_tile : smem_ysum;

    k_prep<<<NCON * NCHUNK, 256>>>(Wsel, mu, upd, dgn);

    cudaFuncSetAttribute(gloce_main,
                         cudaFuncAttributeMaxDynamicSharedMemorySize, (int)smem);
    gloce_main<<<grid, NT, smem>>>(x, center, slope, bias_w, debias, out);
}